// round 2
// baseline (speedup 1.0000x reference)
#include <cuda_runtime.h>
#include <cuda_bf16.h>

// I_MLP_7206955123212: B=2^21 independent 10-step tiny-MLP rollouts.
// Two rows per thread; all weights register-resident; prediction nets
// algebraically fused (fc2@fc1 -> 2x4 affine) with the s_star contribution
// folded into per-row constants. tanh via HW tanh.approx.f32 (MUFU.TANH).

__device__ __forceinline__ float tanh_fast(float x) {
    float y;
    asm("tanh.approx.f32 %0, %1;" : "=f"(y) : "f"(x));
    return y;
}

#define ROWS_PER_THREAD 2

__global__ void __launch_bounds__(128)
rollout_kernel(const float* __restrict__ s_star,
               const float* __restrict__ s0,
               const float* __restrict__ fc1_w, const float* __restrict__ fc1_b,
               const float* __restrict__ fc2_w, const float* __restrict__ fc2_b,
               const float* __restrict__ rc1_w, const float* __restrict__ rc1_b,
               const float* __restrict__ rc2_w, const float* __restrict__ rc2_b,
               const float* __restrict__ rc3_w, const float* __restrict__ rc3_b,
               const float* __restrict__ hf1_w, const float* __restrict__ hf1_b,
               const float* __restrict__ hf2_w, const float* __restrict__ hf2_b,
               float* __restrict__ out, int B)
{
    const int base = (blockIdx.x * blockDim.x + threadIdx.x) * ROWS_PER_THREAD;
    if (base >= B) return;

    // ---- Row-invariant: fuse prediction nets. No activation between fc1 and
    // fc2, so  out = tanh( x @ (W2 W1)^T + (W2 b1 + b2) ).  With x=[s,s_star],
    // split W_eff into the s-half (Wf/Wh) and the s_star-half (folded below).
    float Wf[2][2], WfS[2][2], Bf[2];   // fc net (trainable path)
    float Wh[2][2], WhS[2][2], Bh[2];   // hf net (detached path)
    #pragma unroll
    for (int r = 0; r < 2; ++r) {
        #pragma unroll
        for (int k = 0; k < 4; ++k) {
            float af = 0.f, ah = 0.f;
            #pragma unroll
            for (int j = 0; j < 4; ++j) {
                af = fmaf(fc2_w[r * 4 + j], fc1_w[j * 4 + k], af);
                ah = fmaf(hf2_w[r * 4 + j], hf1_w[j * 4 + k], ah);
            }
            if (k < 2) { Wf[r][k] = af;      Wh[r][k] = ah; }
            else       { WfS[r][k - 2] = af; WhS[r][k - 2] = ah; }
        }
        float bf = fc2_b[r], bh = hf2_b[r];
        #pragma unroll
        for (int j = 0; j < 4; ++j) {
            bf = fmaf(fc2_w[r * 4 + j], fc1_b[j], bf);
            bh = fmaf(hf2_w[r * 4 + j], hf1_b[j], bh);
        }
        Bf[r] = bf; Bh[r] = bh;
    }

    // ---- rc net weights into registers (uniform, L1/const-cache resident)
    float w1[8][4], b1v[8], w2[8][8], b2v[8], w3[2][8], b3v[2];
    #pragma unroll
    for (int j = 0; j < 8; ++j) {
        #pragma unroll
        for (int k = 0; k < 4; ++k) w1[j][k] = rc1_w[j * 4 + k];
        b1v[j] = rc1_b[j];
        #pragma unroll
        for (int k = 0; k < 8; ++k) w2[j][k] = rc2_w[j * 8 + k];
        b2v[j] = rc2_b[j];
    }
    #pragma unroll
    for (int r = 0; r < 2; ++r) {
        #pragma unroll
        for (int k = 0; k < 8; ++k) w3[r][k] = rc3_w[r * 8 + k];
        b3v[r] = rc3_b[r];
    }

    // ---- Two independent rollouts per thread (ILP across rows)
    #pragma unroll
    for (int rr = 0; rr < ROWS_PER_THREAD; ++rr) {
        const int i = base + rr;
        if (i >= B) break;

        const float2 ss = reinterpret_cast<const float2*>(s_star)[i];
        float2 s = reinterpret_cast<const float2*>(s0)[i];

        // Fold s_star half of the fused prediction affine into constants.
        float Cf0 = fmaf(WfS[0][0], ss.x, fmaf(WfS[0][1], ss.y, Bf[0]));
        float Cf1 = fmaf(WfS[1][0], ss.x, fmaf(WfS[1][1], ss.y, Bf[1]));
        float Ch0 = fmaf(WhS[0][0], ss.x, fmaf(WhS[0][1], ss.y, Bh[0]));
        float Ch1 = fmaf(WhS[1][0], ss.x, fmaf(WhS[1][1], ss.y, Bh[1]));

        float err = 0.f;

        #pragma unroll
        for (int t = 0; t < 10; ++t) {
            // fused prediction nets: 4 FMA + 2 tanh each
            float ah0  = tanh_fast(fmaf(Wf[0][0], s.x, fmaf(Wf[0][1], s.y, Cf0)));
            float ah1  = tanh_fast(fmaf(Wf[1][0], s.x, fmaf(Wf[1][1], s.y, Cf1)));
            float ahh0 = tanh_fast(fmaf(Wh[0][0], s.x, fmaf(Wh[0][1], s.y, Ch0)));
            float ahh1 = tanh_fast(fmaf(Wh[1][0], s.x, fmaf(Wh[1][1], s.y, Ch1)));

            // rc1: ctx = [s, ah] -> 8
            float h1[8];
            #pragma unroll
            for (int j = 0; j < 8; ++j)
                h1[j] = tanh_fast(fmaf(w1[j][0], s.x,
                                  fmaf(w1[j][1], s.y,
                                  fmaf(w1[j][2], ah0,
                                  fmaf(w1[j][3], ah1, b1v[j])))));

            // rc2: 8 -> 8
            float h2[8];
            #pragma unroll
            for (int j = 0; j < 8; ++j) {
                float a = b2v[j];
                #pragma unroll
                for (int k = 0; k < 8; ++k) a = fmaf(w2[j][k], h1[k], a);
                h2[j] = tanh_fast(a);
            }

            // rc3: 8 -> 2, state update
            float ar0 = b3v[0], ar1 = b3v[1];
            #pragma unroll
            for (int k = 0; k < 8; ++k) {
                ar0 = fmaf(w3[0][k], h2[k], ar0);
                ar1 = fmaf(w3[1][k], h2[k], ar1);
            }
            s.x = fmaf(0.1f, ar0, s.x);
            s.y = fmaf(0.1f, ar1, s.y);

            // error terms
            float dx = s.x - ss.x, dy = s.y - ss.y;
            err += fmaf(dx, dx, dy * dy);
            err += tanh_fast(ah0) + tanh_fast(ah1);
            err += sqrtf(fmaf(ah0, ah0, ah1 * ah1));
            float e0 = ah0 - ahh0, e1 = ah1 - ahh1;
            err += sqrtf(fmaf(e0, e0, e1 * e1));
        }

        out[i] = err;
    }
}

extern "C" void kernel_launch(void* const* d_in, const int* in_sizes, int n_in,
                              void* d_out, int out_size)
{
    const float* s_star = (const float*)d_in[0];
    const float* s0     = (const float*)d_in[1];
    const float* fc1_w  = (const float*)d_in[2];
    const float* fc1_b  = (const float*)d_in[3];
    const float* fc2_w  = (const float*)d_in[4];
    const float* fc2_b  = (const float*)d_in[5];
    const float* rc1_w  = (const float*)d_in[6];
    const float* rc1_b  = (const float*)d_in[7];
    const float* rc2_w  = (const float*)d_in[8];
    const float* rc2_b  = (const float*)d_in[9];
    const float* rc3_w  = (const float*)d_in[10];
    const float* rc3_b  = (const float*)d_in[11];
    const float* hf1_w  = (const float*)d_in[12];
    const float* hf1_b  = (const float*)d_in[13];
    const float* hf2_w  = (const float*)d_in[14];
    const float* hf2_b  = (const float*)d_in[15];
    float* out = (float*)d_out;

    const int B = out_size;  // one err per row
    const int threads = 128;
    const int rows_per_block = threads * ROWS_PER_THREAD;
    const int blocks = (B + rows_per_block - 1) / rows_per_block;

    rollout_kernel<<<blocks, threads>>>(
        s_star, s0, fc1_w, fc1_b, fc2_w, fc2_b,
        rc1_w, rc1_b, rc2_w, rc2_b, rc3_w, rc3_b,
        hf1_w, hf1_b, hf2_w, hf2_b, out, B);
}

// round 4
// speedup vs baseline: 1.0295x; 1.0295x over previous
#include <cuda_runtime.h>
#include <cuda_bf16.h>

// I_MLP_7206955123212 — B=2^21 independent 10-step tiny-MLP rollouts.
// f32x2 (FFMA2) neuron-pair packing, rc2 weights in smem (broadcast LDS.64),
// prediction nets algebraically fused (no activation between fc1/fc2) with the
// s_star half folded per-row, HW tanh.approx + sqrt.approx. Two rows/thread.

typedef unsigned long long u64;

__device__ __forceinline__ u64 pk2(float lo, float hi) {
    u64 r; asm("mov.b64 %0,{%1,%2};" : "=l"(r) : "f"(lo), "f"(hi)); return r;
}
__device__ __forceinline__ void upk2(u64 v, float& lo, float& hi) {
    asm("mov.b64 {%0,%1},%2;" : "=f"(lo), "=f"(hi) : "l"(v));
}
__device__ __forceinline__ u64 splat(float x) {
    u64 r; asm("mov.b64 %0,{%1,%1};" : "=l"(r) : "f"(x)); return r;
}
__device__ __forceinline__ u64 fma2(u64 a, u64 b, u64 c) {
    u64 d; asm("fma.rn.f32x2 %0,%1,%2,%3;" : "=l"(d) : "l"(a), "l"(b), "l"(c)); return d;
}
__device__ __forceinline__ float tanh_fast(float x) {
    float y; asm("tanh.approx.f32 %0,%1;" : "=f"(y) : "f"(x)); return y;
}
__device__ __forceinline__ float sqrt_fast(float x) {
    float y; asm("sqrt.approx.f32 %0,%1;" : "=f"(y) : "f"(x)); return y;
}

// Packed weight buffer, filled by prep_kernel:
//  [0..1]  WfP col0/col1 (s half)      [2..3]  WhP col0/col1
//  [4..5]  WfS col2/col3 (s_star half) [6..7]  WhS col2/col3
//  [8]     Bf pair        [9] Bh pair
//  [10..25] rc1 w pairs (j2*4+k)       [26..29] rc1 b pairs
//  [30..61] rc2 w pairs (j2*8+k)       [62..65] rc2 b pairs
//  [66..73] rc3 w pairs (k)            [74]     rc3 b pair
__device__ u64 g_pk[80];

__global__ void prep_kernel(const float* __restrict__ fc1_w, const float* __restrict__ fc1_b,
                            const float* __restrict__ fc2_w, const float* __restrict__ fc2_b,
                            const float* __restrict__ rc1_w, const float* __restrict__ rc1_b,
                            const float* __restrict__ rc2_w, const float* __restrict__ rc2_b,
                            const float* __restrict__ rc3_w, const float* __restrict__ rc3_b,
                            const float* __restrict__ hf1_w, const float* __restrict__ hf1_b,
                            const float* __restrict__ hf2_w, const float* __restrict__ hf2_b)
{
    if (threadIdx.x != 0 || blockIdx.x != 0) return;

    // Fuse fc2@fc1 and hf2@hf1 (no activation between) into 2x4 affines.
    float Wf[2][4], Wh[2][4], Bf[2], Bh[2];
    for (int r = 0; r < 2; ++r) {
        for (int k = 0; k < 4; ++k) {
            float af = 0.f, ah = 0.f;
            for (int j = 0; j < 4; ++j) {
                af = fmaf(fc2_w[r * 4 + j], fc1_w[j * 4 + k], af);
                ah = fmaf(hf2_w[r * 4 + j], hf1_w[j * 4 + k], ah);
            }
            Wf[r][k] = af; Wh[r][k] = ah;
        }
        float bf = fc2_b[r], bh = hf2_b[r];
        for (int j = 0; j < 4; ++j) {
            bf = fmaf(fc2_w[r * 4 + j], fc1_b[j], bf);
            bh = fmaf(hf2_w[r * 4 + j], hf1_b[j], bh);
        }
        Bf[r] = bf; Bh[r] = bh;
    }
    g_pk[0] = pk2(Wf[0][0], Wf[1][0]);  g_pk[1] = pk2(Wf[0][1], Wf[1][1]);
    g_pk[2] = pk2(Wh[0][0], Wh[1][0]);  g_pk[3] = pk2(Wh[0][1], Wh[1][1]);
    g_pk[4] = pk2(Wf[0][2], Wf[1][2]);  g_pk[5] = pk2(Wf[0][3], Wf[1][3]);
    g_pk[6] = pk2(Wh[0][2], Wh[1][2]);  g_pk[7] = pk2(Wh[0][3], Wh[1][3]);
    g_pk[8] = pk2(Bf[0], Bf[1]);        g_pk[9] = pk2(Bh[0], Bh[1]);

    for (int j2 = 0; j2 < 4; ++j2) {
        for (int k = 0; k < 4; ++k)
            g_pk[10 + j2 * 4 + k] = pk2(rc1_w[(2 * j2) * 4 + k], rc1_w[(2 * j2 + 1) * 4 + k]);
        g_pk[26 + j2] = pk2(rc1_b[2 * j2], rc1_b[2 * j2 + 1]);
        for (int k = 0; k < 8; ++k)
            g_pk[30 + j2 * 8 + k] = pk2(rc2_w[(2 * j2) * 8 + k], rc2_w[(2 * j2 + 1) * 8 + k]);
        g_pk[62 + j2] = pk2(rc2_b[2 * j2], rc2_b[2 * j2 + 1]);
    }
    for (int k = 0; k < 8; ++k)
        g_pk[66 + k] = pk2(rc3_w[k], rc3_w[8 + k]);
    g_pk[74] = pk2(rc3_b[0], rc3_b[1]);
}

#define RPT 2

__global__ void __launch_bounds__(256)
rollout_kernel(const float* __restrict__ s_star, const float* __restrict__ s0,
               float* __restrict__ out, int B)
{
    // rc2 weights+biases live in smem: g_pk[30..65] (contiguous)
    __shared__ u64 smw[36];
    for (int i = threadIdx.x; i < 36; i += blockDim.x) smw[i] = g_pk[30 + i];
    __syncthreads();

    const int base = (blockIdx.x * blockDim.x + threadIdx.x) * RPT;
    if (base >= B) return;

    const u64 WfP0 = g_pk[0], WfP1 = g_pk[1], WhP0 = g_pk[2], WhP1 = g_pk[3];
    u64 w1p[16], b1p[4], w3p[8];
    #pragma unroll
    for (int i = 0; i < 16; ++i) w1p[i] = g_pk[10 + i];
    #pragma unroll
    for (int i = 0; i < 4; ++i)  b1p[i] = g_pk[26 + i];
    #pragma unroll
    for (int i = 0; i < 8; ++i)  w3p[i] = g_pk[66 + i];
    const u64 b3p = g_pk[74];

    float sx[RPT], sy[RPT], ssx[RPT], ssy[RPT], err[RPT];
    u64 CfP[RPT], ChP[RPT];
    #pragma unroll
    for (int r = 0; r < RPT; ++r) {
        const int i = base + r < B ? base + r : B - 1;
        const float2 ssv = reinterpret_cast<const float2*>(s_star)[i];
        const float2 s0v = reinterpret_cast<const float2*>(s0)[i];
        ssx[r] = ssv.x; ssy[r] = ssv.y;
        sx[r] = s0v.x;  sy[r] = s0v.y;  err[r] = 0.f;
        // Fold the s_star half of the fused prediction affines into per-row consts
        CfP[r] = fma2(g_pk[4], splat(ssv.x), fma2(g_pk[5], splat(ssv.y), g_pk[8]));
        ChP[r] = fma2(g_pk[6], splat(ssv.x), fma2(g_pk[7], splat(ssv.y), g_pk[9]));
    }

    #pragma unroll
    for (int t = 0; t < 10; ++t) {
        #pragma unroll
        for (int r = 0; r < RPT; ++r) {
            const u64 sxS = splat(sx[r]), syS = splat(sy[r]);

            // fused prediction nets: 2 FFMA2 each (outputs packed over neuron dim)
            const u64 af = fma2(WfP0, sxS, fma2(WfP1, syS, CfP[r]));
            const u64 ag = fma2(WhP0, sxS, fma2(WhP1, syS, ChP[r]));
            float f0, f1, g0, g1;
            upk2(af, f0, f1); upk2(ag, g0, g1);
            const float ah0 = tanh_fast(f0),  ah1 = tanh_fast(f1);
            const float ahh0 = tanh_fast(g0), ahh1 = tanh_fast(g1);
            const u64 a0S = splat(ah0), a1S = splat(ah1);

            // rc1: [s, ah] -> 8, neuron pairs
            u64 h1S[8];
            #pragma unroll
            for (int j2 = 0; j2 < 4; ++j2) {
                u64 a = fma2(w1p[j2 * 4 + 0], sxS,
                        fma2(w1p[j2 * 4 + 1], syS,
                        fma2(w1p[j2 * 4 + 2], a0S,
                        fma2(w1p[j2 * 4 + 3], a1S, b1p[j2]))));
                float x0, x1; upk2(a, x0, x1);
                h1S[2 * j2]     = splat(tanh_fast(x0));
                h1S[2 * j2 + 1] = splat(tanh_fast(x1));
            }

            // rc2: 8 -> 8, weights broadcast from smem
            u64 h2S[8];
            #pragma unroll
            for (int j2 = 0; j2 < 4; ++j2) {
                u64 a = smw[32 + j2];
                #pragma unroll
                for (int k = 0; k < 8; ++k) a = fma2(smw[j2 * 8 + k], h1S[k], a);
                float x0, x1; upk2(a, x0, x1);
                h2S[2 * j2]     = splat(tanh_fast(x0));
                h2S[2 * j2 + 1] = splat(tanh_fast(x1));
            }

            // rc3: 8 -> 2 (single pair), state update
            u64 ar = b3p;
            #pragma unroll
            for (int k = 0; k < 8; ++k) ar = fma2(w3p[k], h2S[k], ar);
            float ar0, ar1; upk2(ar, ar0, ar1);
            sx[r] = fmaf(0.1f, ar0, sx[r]);
            sy[r] = fmaf(0.1f, ar1, sy[r]);

            // error terms
            const float dx = sx[r] - ssx[r], dy = sy[r] - ssy[r];
            float e = err[r];
            e += fmaf(dx, dx, dy * dy);
            e += tanh_fast(ah0) + tanh_fast(ah1);
            e += sqrt_fast(fmaf(ah0, ah0, ah1 * ah1));
            const float d0 = ah0 - ahh0, d1 = ah1 - ahh1;
            e += sqrt_fast(fmaf(d0, d0, d1 * d1));
            err[r] = e;
        }
    }

    #pragma unroll
    for (int r = 0; r < RPT; ++r)
        if (base + r < B) out[base + r] = err[r];
}

extern "C" void kernel_launch(void* const* d_in, const int* in_sizes, int n_in,
                              void* d_out, int out_size)
{
    const float* s_star = (const float*)d_in[0];
    const float* s0     = (const float*)d_in[1];
    const float* fc1_w  = (const float*)d_in[2];
    const float* fc1_b  = (const float*)d_in[3];
    const float* fc2_w  = (const float*)d_in[4];
    const float* fc2_b  = (const float*)d_in[5];
    const float* rc1_w  = (const float*)d_in[6];
    const float* rc1_b  = (const float*)d_in[7];
    const float* rc2_w  = (const float*)d_in[8];
    const float* rc2_b  = (const float*)d_in[9];
    const float* rc3_w  = (const float*)d_in[10];
    const float* rc3_b  = (const float*)d_in[11];
    const float* hf1_w  = (const float*)d_in[12];
    const float* hf1_b  = (const float*)d_in[13];
    const float* hf2_w  = (const float*)d_in[14];
    const float* hf2_b  = (const float*)d_in[15];
    float* out = (float*)d_out;

    const int B = out_size;

    prep_kernel<<<1, 1>>>(fc1_w, fc1_b, fc2_w, fc2_b,
                          rc1_w, rc1_b, rc2_w, rc2_b, rc3_w, rc3_b,
                          hf1_w, hf1_b, hf2_w, hf2_b);

    const int threads = 256;
    const int rows_per_block = threads * RPT;
    const int blocks = (B + rows_per_block - 1) / rows_per_block;
    rollout_kernel<<<blocks, threads>>>(s_star, s0, out, B);
}

// round 5
// speedup vs baseline: 1.1457x; 1.1128x over previous
#include <cuda_runtime.h>
#include <cuda_bf16.h>

// I_MLP_7206955123212 — B=2^21 independent 10-step tiny-MLP rollouts.
// Scalar FFMA (f32x2 removed: it split on sm_100a and added ALU mov traffic).
// Occupancy-focused: rc1/rc2/rc3 weights streamed from smem via broadcast
// LDS.128 inside a non-unrolled step loop; only fused prediction weights +
// per-row state stay register-resident. Two rows per thread, step-outer.

__device__ __forceinline__ float tanh_fast(float x) {
    float y; asm("tanh.approx.f32 %0,%1;" : "=f"(y) : "f"(x)); return y;
}
__device__ __forceinline__ float sqrt_fast(float x) {
    float y; asm("sqrt.approx.f32 %0,%1;" : "=f"(y) : "f"(x)); return y;
}

// g_w layout (floats):
//  [0..19]    pred: Wf00,Wf01,Wf10,Wf11, Wh00,Wh01,Wh10,Wh11,
//                   WfS00,WfS01,WfS10,WfS11, WhS00,WhS01,WhS10,WhS11,
//                   Bf0,Bf1,Bh0,Bh1
//  [20..51]   rc1_w (j*4+k)       [52..59]   rc1_b
//  [60..123]  rc2_w (j*8+k)       [124..131] rc2_b
//  [132..147] rc3_w (r*8+k)       [148..149] rc3_b
__device__ float g_w[160];

__global__ void prep_kernel(const float* __restrict__ fc1_w, const float* __restrict__ fc1_b,
                            const float* __restrict__ fc2_w, const float* __restrict__ fc2_b,
                            const float* __restrict__ rc1_w, const float* __restrict__ rc1_b,
                            const float* __restrict__ rc2_w, const float* __restrict__ rc2_b,
                            const float* __restrict__ rc3_w, const float* __restrict__ rc3_b,
                            const float* __restrict__ hf1_w, const float* __restrict__ hf1_b,
                            const float* __restrict__ hf2_w, const float* __restrict__ hf2_b)
{
    if (threadIdx.x != 0 || blockIdx.x != 0) return;

    // Fuse fc2@fc1 and hf2@hf1 (no activation between) into 2x4 affines.
    float Wf[2][4], Wh[2][4], Bf[2], Bh[2];
    for (int r = 0; r < 2; ++r) {
        for (int k = 0; k < 4; ++k) {
            float af = 0.f, ah = 0.f;
            for (int j = 0; j < 4; ++j) {
                af = fmaf(fc2_w[r * 4 + j], fc1_w[j * 4 + k], af);
                ah = fmaf(hf2_w[r * 4 + j], hf1_w[j * 4 + k], ah);
            }
            Wf[r][k] = af; Wh[r][k] = ah;
        }
        float bf = fc2_b[r], bh = hf2_b[r];
        for (int j = 0; j < 4; ++j) {
            bf = fmaf(fc2_w[r * 4 + j], fc1_b[j], bf);
            bh = fmaf(hf2_w[r * 4 + j], hf1_b[j], bh);
        }
        Bf[r] = bf; Bh[r] = bh;
    }
    // pred: s-half (cols 0,1), s_star-half (cols 2,3), fused biases
    g_w[0] = Wf[0][0]; g_w[1] = Wf[0][1]; g_w[2] = Wf[1][0]; g_w[3] = Wf[1][1];
    g_w[4] = Wh[0][0]; g_w[5] = Wh[0][1]; g_w[6] = Wh[1][0]; g_w[7] = Wh[1][1];
    g_w[8]  = Wf[0][2]; g_w[9]  = Wf[0][3]; g_w[10] = Wf[1][2]; g_w[11] = Wf[1][3];
    g_w[12] = Wh[0][2]; g_w[13] = Wh[0][3]; g_w[14] = Wh[1][2]; g_w[15] = Wh[1][3];
    g_w[16] = Bf[0]; g_w[17] = Bf[1]; g_w[18] = Bh[0]; g_w[19] = Bh[1];

    for (int i = 0; i < 32; ++i) g_w[20 + i]  = rc1_w[i];
    for (int i = 0; i < 8;  ++i) g_w[52 + i]  = rc1_b[i];
    for (int i = 0; i < 64; ++i) g_w[60 + i]  = rc2_w[i];
    for (int i = 0; i < 8;  ++i) g_w[124 + i] = rc2_b[i];
    for (int i = 0; i < 16; ++i) g_w[132 + i] = rc3_w[i];
    for (int i = 0; i < 2;  ++i) g_w[148 + i] = rc3_b[i];
}

#define RPT 2

__global__ void __launch_bounds__(128, 5)
rollout_kernel(const float* __restrict__ s_star, const float* __restrict__ s0,
               float* __restrict__ out, int B)
{
    // smem: pred (20) at [0..19], then rc blocks copied 1:1 from g_w[20..149]
    // into s_w[0..129]:  rc1w @0 (float4-aligned), rc1b @32, rc2w @40
    // (40*4=160B, 16B-aligned), rc2b @104, rc3w @112 (448B, aligned), rc3b @128.
    __shared__ float s_pred[20];
    __shared__ __align__(16) float s_w[132];
    for (int i = threadIdx.x; i < 150; i += blockDim.x) {
        if (i < 20) s_pred[i] = g_w[i];
        else        s_w[i - 20] = g_w[i];
    }
    __syncthreads();

    const float4* __restrict__ s4_rc1 = reinterpret_cast<const float4*>(s_w + 0);
    const float*  __restrict__ s_rc1b = s_w + 32;
    const float4* __restrict__ s4_rc2 = reinterpret_cast<const float4*>(s_w + 40);
    const float*  __restrict__ s_rc2b = s_w + 104;
    const float4* __restrict__ s4_rc3 = reinterpret_cast<const float4*>(s_w + 112);
    const float*  __restrict__ s_rc3b = s_w + 128;

    const int base = (blockIdx.x * blockDim.x + threadIdx.x) * RPT;
    if (base >= B) return;

    // Register-resident: prediction s-half weights + per-row folded constants.
    const float Wf00 = s_pred[0], Wf01 = s_pred[1], Wf10 = s_pred[2], Wf11 = s_pred[3];
    const float Wh00 = s_pred[4], Wh01 = s_pred[5], Wh10 = s_pred[6], Wh11 = s_pred[7];

    float sx[RPT], sy[RPT], ssx[RPT], ssy[RPT], err[RPT];
    float Cf0[RPT], Cf1[RPT], Ch0[RPT], Ch1[RPT];
    #pragma unroll
    for (int r = 0; r < RPT; ++r) {
        const int i = (base + r < B) ? base + r : B - 1;
        const float2 ssv = reinterpret_cast<const float2*>(s_star)[i];
        const float2 s0v = reinterpret_cast<const float2*>(s0)[i];
        ssx[r] = ssv.x; ssy[r] = ssv.y;
        sx[r] = s0v.x;  sy[r] = s0v.y;  err[r] = 0.f;
        Cf0[r] = fmaf(s_pred[8],  ssv.x, fmaf(s_pred[9],  ssv.y, s_pred[16]));
        Cf1[r] = fmaf(s_pred[10], ssv.x, fmaf(s_pred[11], ssv.y, s_pred[17]));
        Ch0[r] = fmaf(s_pred[12], ssv.x, fmaf(s_pred[13], ssv.y, s_pred[18]));
        Ch1[r] = fmaf(s_pred[14], ssv.x, fmaf(s_pred[15], ssv.y, s_pred[19]));
    }

    // Step loop deliberately NOT unrolled: keeps smem weight loads inside the
    // loop body so ptxas can't hoist them into long-lived registers.
    #pragma unroll 1
    for (int t = 0; t < 10; ++t) {
        // fused prediction nets (register weights): 8 FMA + 4 tanh per row
        float ah0[RPT], ah1[RPT], ag0[RPT], ag1[RPT];
        #pragma unroll
        for (int r = 0; r < RPT; ++r) {
            ah0[r] = tanh_fast(fmaf(Wf00, sx[r], fmaf(Wf01, sy[r], Cf0[r])));
            ah1[r] = tanh_fast(fmaf(Wf10, sx[r], fmaf(Wf11, sy[r], Cf1[r])));
            ag0[r] = tanh_fast(fmaf(Wh00, sx[r], fmaf(Wh01, sy[r], Ch0[r])));
            ag1[r] = tanh_fast(fmaf(Wh10, sx[r], fmaf(Wh11, sy[r], Ch1[r])));
        }

        // rc1: [s, ah] -> 8  (weights broadcast from smem, shared by both rows)
        float h1[RPT][8];
        #pragma unroll
        for (int j = 0; j < 8; ++j) {
            const float4 w = s4_rc1[j];
            const float  b = s_rc1b[j];
            #pragma unroll
            for (int r = 0; r < RPT; ++r)
                h1[r][j] = tanh_fast(fmaf(w.x, sx[r],
                                     fmaf(w.y, sy[r],
                                     fmaf(w.z, ah0[r],
                                     fmaf(w.w, ah1[r], b)))));
        }

        // rc2: 8 -> 8
        float h2[RPT][8];
        #pragma unroll
        for (int j = 0; j < 8; ++j) {
            const float4 wa = s4_rc2[2 * j];
            const float4 wb = s4_rc2[2 * j + 1];
            const float  b  = s_rc2b[j];
            #pragma unroll
            for (int r = 0; r < RPT; ++r) {
                float a = fmaf(wa.x, h1[r][0], fmaf(wa.y, h1[r][1],
                          fmaf(wa.z, h1[r][2], fmaf(wa.w, h1[r][3], b))));
                a = fmaf(wb.x, h1[r][4], fmaf(wb.y, h1[r][5],
                    fmaf(wb.z, h1[r][6], fmaf(wb.w, h1[r][7], a))));
                h2[r][j] = tanh_fast(a);
            }
        }

        // rc3: 8 -> 2, state update, error terms
        const float4 wa0 = s4_rc3[0], wa1 = s4_rc3[1];
        const float4 wb0 = s4_rc3[2], wb1 = s4_rc3[3];
        const float  b30 = s_rc3b[0], b31 = s_rc3b[1];
        #pragma unroll
        for (int r = 0; r < RPT; ++r) {
            float ar0 = fmaf(wa0.x, h2[r][0], fmaf(wa0.y, h2[r][1],
                        fmaf(wa0.z, h2[r][2], fmaf(wa0.w, h2[r][3], b30))));
            ar0 = fmaf(wa1.x, h2[r][4], fmaf(wa1.y, h2[r][5],
                  fmaf(wa1.z, h2[r][6], fmaf(wa1.w, h2[r][7], ar0))));
            float ar1 = fmaf(wb0.x, h2[r][0], fmaf(wb0.y, h2[r][1],
                        fmaf(wb0.z, h2[r][2], fmaf(wb0.w, h2[r][3], b31))));
            ar1 = fmaf(wb1.x, h2[r][4], fmaf(wb1.y, h2[r][5],
                  fmaf(wb1.z, h2[r][6], fmaf(wb1.w, h2[r][7], ar1))));
            sx[r] = fmaf(0.1f, ar0, sx[r]);
            sy[r] = fmaf(0.1f, ar1, sy[r]);

            const float dx = sx[r] - ssx[r], dy = sy[r] - ssy[r];
            float e = err[r];
            e += fmaf(dx, dx, dy * dy);
            e += tanh_fast(ah0[r]) + tanh_fast(ah1[r]);
            e += sqrt_fast(fmaf(ah0[r], ah0[r], ah1[r] * ah1[r]));
            const float d0 = ah0[r] - ag0[r], d1 = ah1[r] - ag1[r];
            e += sqrt_fast(fmaf(d0, d0, d1 * d1));
            err[r] = e;
        }
    }

    #pragma unroll
    for (int r = 0; r < RPT; ++r)
        if (base + r < B) out[base + r] = err[r];
}

extern "C" void kernel_launch(void* const* d_in, const int* in_sizes, int n_in,
                              void* d_out, int out_size)
{
    const float* s_star = (const float*)d_in[0];
    const float* s0     = (const float*)d_in[1];
    const float* fc1_w  = (const float*)d_in[2];
    const float* fc1_b  = (const float*)d_in[3];
    const float* fc2_w  = (const float*)d_in[4];
    const float* fc2_b  = (const float*)d_in[5];
    const float* rc1_w  = (const float*)d_in[6];
    const float* rc1_b  = (const float*)d_in[7];
    const float* rc2_w  = (const float*)d_in[8];
    const float* rc2_b  = (const float*)d_in[9];
    const float* rc3_w  = (const float*)d_in[10];
    const float* rc3_b  = (const float*)d_in[11];
    const float* hf1_w  = (const float*)d_in[12];
    const float* hf1_b  = (const float*)d_in[13];
    const float* hf2_w  = (const float*)d_in[14];
    const float* hf2_b  = (const float*)d_in[15];
    float* out = (float*)d_out;

    const int B = out_size;

    prep_kernel<<<1, 1>>>(fc1_w, fc1_b, fc2_w, fc2_b,
                          rc1_w, rc1_b, rc2_w, rc2_b, rc3_w, rc3_b,
                          hf1_w, hf1_b, hf2_w, hf2_b);

    const int threads = 128;
    const int rows_per_block = threads * RPT;
    const int blocks = (B + rows_per_block - 1) / rows_per_block;
    rollout_kernel<<<blocks, threads>>>(s_star, s0, out, B);
}